// round 8
// baseline (speedup 1.0000x reference)
#include <cuda_runtime.h>

#define LAM 0.95f
#define ETA 0.5f
#define B_SZ 128
#define D_SZ 1024
#define ROWS_PER_BLK 4

// out[b,i,j] = LAM*A[b,i,j] + ETA*h[b,i]*h[b,j]
// R2 concurrency recipe (256 thr, 32768 blocks, 64 front-batched bytes/thread,
// evict-first) but with Blackwell 256-bit global accesses: each thread moves
// two 32-byte chunks (rows t>>7 and t>>7 + 2 of the block's 4-row strip).
// Hypothesis: 32B-granular requests lengthen HBM bursts in the
// read/write-turnaround-bound regime.

__device__ __forceinline__ void ldcs_v8(const float* p, float* v) {
    asm volatile("ld.global.cs.v8.f32 {%0,%1,%2,%3,%4,%5,%6,%7}, [%8];"
                 : "=f"(v[0]), "=f"(v[1]), "=f"(v[2]), "=f"(v[3]),
                   "=f"(v[4]), "=f"(v[5]), "=f"(v[6]), "=f"(v[7])
                 : "l"(p));
}

__device__ __forceinline__ void stcs_v8(float* p, const float* v) {
    asm volatile("st.global.cs.v8.f32 [%0], {%1,%2,%3,%4,%5,%6,%7,%8};"
                 :: "l"(p),
                    "f"(v[0]), "f"(v[1]), "f"(v[2]), "f"(v[3]),
                    "f"(v[4]), "f"(v[5]), "f"(v[6]), "f"(v[7])
                 : "memory");
}

__global__ void __launch_bounds__(256) fastweight_kernel(
    const float* __restrict__ A,
    const float* __restrict__ h,
    float* __restrict__ out)
{
    int blk = blockIdx.x;
    int b  = blk >> 8;                    // 256 row-groups per batch (1024/4)
    int rg = blk & 255;
    int i0 = rg * ROWS_PER_BLK;
    int t  = threadIdx.x;

    int row0 = t >> 7;                    // 0 or 1 (rows row0 and row0+2)
    int col8 = t & 127;                   // 32B chunk within the row

    // float index of chunk in row (i0+row0): fits 32-bit
    int base0 = (b * D_SZ + i0 + row0) * D_SZ + col8 * 8;
    int base1 = base0 + 2 * D_SZ;         // row0 + 2

    // hj: 8 consecutive h values for this chunk's columns (L1/L2 resident)
    const float4* hB = (const float4*)(h + b * D_SZ) + col8 * 2;
    float4 hj0 = __ldg(hB + 0);
    float4 hj1 = __ldg(hB + 1);

    float hiA = __ldg(h + b * D_SZ + i0 + row0)     * ETA;
    float hiB = __ldg(h + b * D_SZ + i0 + row0 + 2) * ETA;

    // Front-batch both 256-bit streaming loads (64B outstanding / thread)
    float a0[8], a1[8];
    ldcs_v8(A + base0, a0);
    ldcs_v8(A + base1, a1);

    float r[8];
    r[0] = fmaf(hiA, hj0.x, a0[0] * LAM);
    r[1] = fmaf(hiA, hj0.y, a0[1] * LAM);
    r[2] = fmaf(hiA, hj0.z, a0[2] * LAM);
    r[3] = fmaf(hiA, hj0.w, a0[3] * LAM);
    r[4] = fmaf(hiA, hj1.x, a0[4] * LAM);
    r[5] = fmaf(hiA, hj1.y, a0[5] * LAM);
    r[6] = fmaf(hiA, hj1.z, a0[6] * LAM);
    r[7] = fmaf(hiA, hj1.w, a0[7] * LAM);
    stcs_v8(out + base0, r);

    r[0] = fmaf(hiB, hj0.x, a1[0] * LAM);
    r[1] = fmaf(hiB, hj0.y, a1[1] * LAM);
    r[2] = fmaf(hiB, hj0.z, a1[2] * LAM);
    r[3] = fmaf(hiB, hj0.w, a1[3] * LAM);
    r[4] = fmaf(hiB, hj1.x, a1[4] * LAM);
    r[5] = fmaf(hiB, hj1.y, a1[5] * LAM);
    r[6] = fmaf(hiB, hj1.z, a1[6] * LAM);
    r[7] = fmaf(hiB, hj1.w, a1[7] * LAM);
    stcs_v8(out + base1, r);
}

extern "C" void kernel_launch(void* const* d_in, const int* in_sizes, int n_in,
                              void* d_out, int out_size) {
    const float* A = (const float*)d_in[0];
    const float* h = (const float*)d_in[1];
    float* out = (float*)d_out;

    // grid = B * (D / 4) = 128 * 256 = 32768 blocks
    int blocks = B_SZ * (D_SZ / ROWS_PER_BLK);
    fastweight_kernel<<<blocks, 256>>>(A, h, out);
}